// round 10
// baseline (speedup 1.0000x reference)
#include <cuda_runtime.h>
#include <cuda_fp16.h>
#include <stdint.h>
#include <math.h>

// ---------------- problem constants ----------------
constexpr int B_  = 4;
constexpr int S_  = 9;
constexpr int D_  = 256;
constexpr int NH_ = 16;
constexpr int DK_ = 16;
constexpr int QL_ = 1024;   // 32*32
constexpr int KL_ = 2304;   // 9*16*16

// ---------------- scratch (no cudaMalloc allowed) ----------------
__device__ float  g_vn [B_ * KL_ * D_];         // (b, kl, d)  post conv+GN
__device__ float  g_v  [B_ * KL_ * D_];         // (b, kl, d)  V fp32 (pre-transpose)
__device__ float  g_ao [B_ * QL_ * D_];         // (b, q, h*dk) attention output
__device__ __half g_q16h[B_ * NH_ * QL_ * DK_]; // (bh, q, dk) Q fp16 (pre-scaled x0.25)
__device__ __half g_k16 [B_ * NH_ * KL_ * DK_]; // (bh, kl, dk) K fp16
__device__ __half g_vth [B_ * NH_ * DK_ * KL_]; // (bh, dk, kl) V^T fp16

__device__ __forceinline__ uint32_t h2u(__half2 h) {
    return *reinterpret_cast<uint32_t*>(&h);
}

// fp32-accum fp16 mma: D = A(16x16) * B(16x8) + D
__device__ __forceinline__ void mma16816(float* c, const uint32_t* a,
                                         uint32_t b0, uint32_t b1) {
    asm volatile(
        "mma.sync.aligned.m16n8k16.row.col.f32.f16.f16.f32 "
        "{%0,%1,%2,%3}, {%4,%5,%6,%7}, {%8,%9}, {%0,%1,%2,%3};\n"
        : "+f"(c[0]), "+f"(c[1]), "+f"(c[2]), "+f"(c[3])
        : "r"(a[0]), "r"(a[1]), "r"(a[2]), "r"(a[3]), "r"(b0), "r"(b1));
}

__device__ __forceinline__ void split2(float a, float b, __half2& h, __half2& l) {
    h = __floats2half2_rn(a, b);
    l = __floats2half2_rn(a - __low2float(h), b - __high2float(h));
}

// =====================================================================
// Kernel 1: HMMA conv(2x2,s2) + bias + fused GroupNorm.
// 2-term compensation: Ah*Bh + Ah*Bl. grid=(4, 36), block=256.
// =====================================================================
__global__ __launch_bounds__(256, 1)
void conv_gn_mma_kernel(const float* __restrict__ x,
                        const float* __restrict__ cw,
                        const float* __restrict__ cb,
                        const float* __restrict__ gng,
                        const float* __restrict__ gnb) {
    const int nb  = blockIdx.x;              // oc quarter (64 oc)
    const int bs  = blockIdx.y;              // image
    const int bb  = bs / 9, ss = bs % 9;
    const int tid = threadIdx.x;
    const int wid = tid >> 5, lane = tid & 31;
    const int g   = lane >> 2, tg = lane & 3;
    const int wm  = wid & 3, wn = wid >> 2;
    const int pi  = tid >> 4, pj = tid & 15;
    const int n0  = nb * 64;

    __shared__ __half Ah[256][36];
    __shared__ __half Bh[64][36],  Bl[64][36];
    __shared__ float  sred[8];
    __shared__ float  sstat[8];

    if (tid < 8) sred[tid] = 0.f;

    float acc[4][4][4];
#pragma unroll
    for (int a = 0; a < 4; ++a)
#pragma unroll
        for (int b = 0; b < 4; ++b)
#pragma unroll
            for (int e = 0; e < 4; ++e) acc[a][b][e] = 0.f;

    const float* xb = x + (size_t)bs * (256 * 1024);

    for (int ch = 0; ch < 32; ++ch) {
        const int k0 = ch * 32;
        __syncthreads();
        const float* xrow = xb + (size_t)(ch * 8) * 1024 + (2 * pi) * 32 + 2 * pj;
#pragma unroll
        for (int kk = 0; kk < 32; kk += 2) {
            const int ic = kk >> 2, dy = (kk >> 1) & 1;
            float2 v = *(const float2*)(xrow + ic * 1024 + dy * 32);
            *(__half2*)&Ah[tid][kk] = __floats2half2_rn(v.x, v.y);
        }
#pragma unroll
        for (int i = 0; i < 2; ++i) {
            const int idx = tid * 2 + i;
            const int oc = idx >> 3, j = (idx & 7) * 4;
            float4 wv = *(const float4*)(cw + (size_t)(n0 + oc) * 1024 + k0 + j);
            __half2 h01, l01, h23, l23;
            split2(wv.x, wv.y, h01, l01);
            split2(wv.z, wv.w, h23, l23);
            *(__half2*)&Bh[oc][j]     = h01;
            *(__half2*)&Bh[oc][j + 2] = h23;
            *(__half2*)&Bl[oc][j]     = l01;
            *(__half2*)&Bl[oc][j + 2] = l23;
        }
        __syncthreads();

#pragma unroll
        for (int ks = 0; ks < 2; ++ks) {
            const int kc = ks * 16 + 2 * tg;
            uint32_t aH[4][4];
#pragma unroll
            for (int mt = 0; mt < 4; ++mt) {
                const int r = wm * 64 + mt * 16 + g;
                aH[mt][0] = *(uint32_t*)&Ah[r][kc];
                aH[mt][1] = *(uint32_t*)&Ah[r + 8][kc];
                aH[mt][2] = *(uint32_t*)&Ah[r][kc + 8];
                aH[mt][3] = *(uint32_t*)&Ah[r + 8][kc + 8];
            }
#pragma unroll
            for (int nt = 0; nt < 4; ++nt) {
                const int c = wn * 32 + nt * 8 + g;
                uint32_t bh0 = *(uint32_t*)&Bh[c][kc];
                uint32_t bh1 = *(uint32_t*)&Bh[c][kc + 8];
                uint32_t bl0 = *(uint32_t*)&Bl[c][kc];
                uint32_t bl1 = *(uint32_t*)&Bl[c][kc + 8];
#pragma unroll
                for (int mt = 0; mt < 4; ++mt) {
                    mma16816(acc[mt][nt], aH[mt], bh0, bh1);
                    mma16816(acc[mt][nt], aH[mt], bl0, bl1);
                }
            }
        }
    }

    float gsum[2] = {0.f, 0.f}, gsq[2] = {0.f, 0.f};
#pragma unroll
    for (int nt = 0; nt < 4; ++nt) {
        const int col = n0 + wn * 32 + nt * 8 + 2 * tg;
        const float b0 = cb[col], b1 = cb[col + 1];
#pragma unroll
        for (int mt = 0; mt < 4; ++mt) {
            float* c = acc[mt][nt];
            c[0] += b0; c[1] += b1; c[2] += b0; c[3] += b1;
            gsum[nt >> 1] += (c[0] + c[1]) + (c[2] + c[3]);
            gsq[nt >> 1]  += (c[0]*c[0] + c[1]*c[1]) + (c[2]*c[2] + c[3]*c[3]);
        }
    }
#pragma unroll
    for (int i = 0; i < 2; ++i)
#pragma unroll
        for (int off = 16; off; off >>= 1) {
            gsum[i] += __shfl_xor_sync(0xffffffffu, gsum[i], off);
            gsq[i]  += __shfl_xor_sync(0xffffffffu, gsq[i],  off);
        }
    if (lane == 0) {
#pragma unroll
        for (int i = 0; i < 2; ++i) {
            const int gi = wn * 2 + i;
            atomicAdd(&sred[gi * 2],     gsum[i]);
            atomicAdd(&sred[gi * 2 + 1], gsq[i]);
        }
    }
    __syncthreads();
    if (tid < 4) {
        const float mu  = sred[tid * 2] * (1.f / 4096.f);
        const float var = sred[tid * 2 + 1] * (1.f / 4096.f) - mu * mu;
        sstat[tid * 2]     = mu;
        sstat[tid * 2 + 1] = rsqrtf(var + 1e-5f);
    }
    __syncthreads();

    float* dstb = g_vn + ((size_t)bb * KL_ + ss * 256) * 256;
#pragma unroll
    for (int nt = 0; nt < 4; ++nt) {
        const int gi = wn * 2 + (nt >> 1);
        const float mu = sstat[gi * 2], rstd = sstat[gi * 2 + 1];
        const int col = n0 + wn * 32 + nt * 8 + 2 * tg;
        const float s0 = rstd * gng[col],     o0 = gnb[col]     - mu * s0;
        const float s1 = rstd * gng[col + 1], o1 = gnb[col + 1] - mu * s1;
#pragma unroll
        for (int mt = 0; mt < 4; ++mt) {
            const int r = wm * 64 + mt * 16 + g;
            const float* c = acc[mt][nt];
            *(float2*)(dstb + (size_t)r * 256 + col) =
                make_float2(c[0] * s0 + o0, c[1] * s1 + o1);
            *(float2*)(dstb + (size_t)(r + 8) * 256 + col) =
                make_float2(c[2] * s0 + o0, c[3] * s1 + o1);
        }
    }
}

// =====================================================================
// Tensor-core batched GEMM, tile M=128 N=64, K=256 in chunks of 32.
// MODE 0: Q    = x[:,4]^T @ wq   -> fp16 head-major, PRE-SCALED x0.25
// MODE 1: KV   = g_vn @ wkv      -> K fp16 head-major, V fp32 (b,kl,d)
// MODE 2: proj = g_ao @ proj_w   -> transposed fp32 store (NCHW out)
// =====================================================================
template <int MODE>
__global__ __launch_bounds__(256, 2)
void gemm_mma_kernel(const float* __restrict__ Aext,
                     const float* __restrict__ Bw,
                     const float* __restrict__ bias,
                     float* __restrict__ Cext) {
    constexpr int N = (MODE == 1) ? 512 : 256;

    const int b  = blockIdx.z;
    const int n0 = blockIdx.x * 64;
    const int m0 = blockIdx.y * 128;
    const int tid = threadIdx.x;
    const int wid = tid >> 5, lane = tid & 31;
    const int g = lane >> 2, tg = lane & 3;
    const int wm = wid & 3, wn = wid >> 2;

    __shared__ __half Ah[128][36], Al[128][36];
    __shared__ __half Bh[64][36],  Bl[64][36];

    const float* Ab;
    if (MODE == 0)      Ab = Aext + ((size_t)(b * 9 + 4)) * (256 * 1024);
    else if (MODE == 1) Ab = g_vn + (size_t)b * (KL_ * D_);
    else                Ab = g_ao + (size_t)b * (QL_ * D_);

    float acc[2][4][4];
#pragma unroll
    for (int a = 0; a < 2; ++a)
#pragma unroll
        for (int c = 0; c < 4; ++c)
#pragma unroll
            for (int e = 0; e < 4; ++e) acc[a][c][e] = 0.f;

    for (int k0 = 0; k0 < 256; k0 += 32) {
        __syncthreads();
        // ---- A staging ----
        if (MODE == 0) {
            const int kk = tid >> 6, mloc = (tid & 63) * 2;
#pragma unroll
            for (int i = 0; i < 8; ++i) {
                const int k = kk + i * 4;
                float2 v = *(const float2*)(Ab + (size_t)(k0 + k) * 1024 + m0 + mloc);
                __half2 h, l;
                split2(v.x, v.y, h, l);
                Ah[mloc][k]     = __low2half(h);
                Ah[mloc + 1][k] = __high2half(h);
                Al[mloc][k]     = __low2half(l);
                Al[mloc + 1][k] = __high2half(l);
            }
        } else {
            const int arow = tid >> 3, c4 = (tid & 7) * 4;
#pragma unroll
            for (int i = 0; i < 4; ++i) {
                const int r = arow + i * 32;
                float4 a4 = *(const float4*)(Ab + (size_t)(m0 + r) * 256 + k0 + c4);
                __half2 h01, l01, h23, l23;
                split2(a4.x, a4.y, h01, l01);
                split2(a4.z, a4.w, h23, l23);
                *(__half2*)&Ah[r][c4]     = h01;
                *(__half2*)&Ah[r][c4 + 2] = h23;
                *(__half2*)&Al[r][c4]     = l01;
                *(__half2*)&Al[r][c4 + 2] = l23;
            }
        }
        // ---- B staging ----
        {
            const int bk2 = (tid >> 4) * 2, bn4 = (tid & 15) * 4;
            float4 u = *(const float4*)(Bw + (size_t)(k0 + bk2) * N + n0 + bn4);
            float4 w = *(const float4*)(Bw + (size_t)(k0 + bk2 + 1) * N + n0 + bn4);
            float uu[4] = {u.x, u.y, u.z, u.w};
            float wwv[4] = {w.x, w.y, w.z, w.w};
#pragma unroll
            for (int j = 0; j < 4; ++j) {
                __half2 h, l;
                split2(uu[j], wwv[j], h, l);
                *(__half2*)&Bh[bn4 + j][bk2] = h;
                *(__half2*)&Bl[bn4 + j][bk2] = l;
            }
        }
        __syncthreads();

#pragma unroll
        for (int ks = 0; ks < 2; ++ks) {
            const int kc = ks * 16 + 2 * tg;
            uint32_t aH[2][4], aL[2][4];
#pragma unroll
            for (int mt = 0; mt < 2; ++mt) {
                const int r = wm * 32 + mt * 16 + g;
                aH[mt][0] = *(uint32_t*)&Ah[r][kc];
                aH[mt][1] = *(uint32_t*)&Ah[r + 8][kc];
                aH[mt][2] = *(uint32_t*)&Ah[r][kc + 8];
                aH[mt][3] = *(uint32_t*)&Ah[r + 8][kc + 8];
                aL[mt][0] = *(uint32_t*)&Al[r][kc];
                aL[mt][1] = *(uint32_t*)&Al[r + 8][kc];
                aL[mt][2] = *(uint32_t*)&Al[r][kc + 8];
                aL[mt][3] = *(uint32_t*)&Al[r + 8][kc + 8];
            }
#pragma unroll
            for (int nt = 0; nt < 4; ++nt) {
                const int c = wn * 32 + nt * 8 + g;
                uint32_t bh0 = *(uint32_t*)&Bh[c][kc];
                uint32_t bh1 = *(uint32_t*)&Bh[c][kc + 8];
                uint32_t bl0 = *(uint32_t*)&Bl[c][kc];
                uint32_t bl1 = *(uint32_t*)&Bl[c][kc + 8];
#pragma unroll
                for (int mt = 0; mt < 2; ++mt) {
                    mma16816(acc[mt][nt], aH[mt], bh0, bh1);
                    mma16816(acc[mt][nt], aL[mt], bh0, bh1);
                    mma16816(acc[mt][nt], aH[mt], bl0, bl1);
                }
            }
        }
    }

    // ---- epilogue ----
#pragma unroll
    for (int nt = 0; nt < 4; ++nt) {
        const int c = n0 + wn * 32 + nt * 8 + 2 * tg;
        const float bl0 = bias[c], bl1 = bias[c + 1];
#pragma unroll
        for (int mt = 0; mt < 2; ++mt) {
            const int r0 = m0 + wm * 32 + mt * 16 + g, r1 = r0 + 8;
            const float* a = acc[mt][nt];
            const float v00 = a[0] + bl0, v01 = a[1] + bl1;
            const float v10 = a[2] + bl0, v11 = a[3] + bl1;
            if (MODE == 2) {
                Cext[((size_t)b * 256 + c) * 1024 + r0]     = v00;
                Cext[((size_t)b * 256 + c + 1) * 1024 + r0] = v01;
                Cext[((size_t)b * 256 + c) * 1024 + r1]     = v10;
                Cext[((size_t)b * 256 + c + 1) * 1024 + r1] = v11;
            } else if (MODE == 0) {
                // fold the softmax 1/sqrt(dk)=0.25 scale into Q (exact: power of 2)
                const int hh = c >> 4, dk = c & 15;
                __half2 h0 = __floats2half2_rn(v00 * 0.25f, v01 * 0.25f);
                __half2 h1 = __floats2half2_rn(v10 * 0.25f, v11 * 0.25f);
                size_t o0 = ((size_t)(b * NH_ + hh) * QL_ + r0) * DK_ + dk;
                size_t o1 = ((size_t)(b * NH_ + hh) * QL_ + r1) * DK_ + dk;
                *(uint32_t*)(g_q16h + o0) = h2u(h0);
                *(uint32_t*)(g_q16h + o1) = h2u(h1);
            } else { // MODE 1
                if (c < 256) {
                    const int hh = c >> 4, dk = c & 15;
                    __half2 h0 = __floats2half2_rn(v00, v01);
                    __half2 h1 = __floats2half2_rn(v10, v11);
                    size_t o0 = ((size_t)(b * NH_ + hh) * KL_ + r0) * DK_ + dk;
                    size_t o1 = ((size_t)(b * NH_ + hh) * KL_ + r1) * DK_ + dk;
                    *(uint32_t*)(g_k16 + o0) = h2u(h0);
                    *(uint32_t*)(g_k16 + o1) = h2u(h1);
                } else {
                    const int d = c - 256;
                    float* C = g_v + (size_t)b * (KL_ * D_);
                    *(float2*)(C + (size_t)r0 * 256 + d) = make_float2(v00, v01);
                    *(float2*)(C + (size_t)r1 * 256 + d) = make_float2(v10, v11);
                }
            }
        }
    }
}

// =====================================================================
// V transpose: fp32 (b,kl,d) -> fp16 (bh, dk, kl)
// grid = (64 bh, 9 kl-chunks), block = 256
// =====================================================================
__global__ void vtrans_kernel() {
    const int bh = blockIdx.x;
    const int b = bh >> 4, h = bh & 15;
    const int kl0 = blockIdx.y * 256;
    const int tid = threadIdx.x;
    __shared__ float tile[256][17];
    const float* src = g_v + (size_t)b * KL_ * D_ + h * 16;
    __half* dh = g_vth + (size_t)bh * DK_ * KL_;

    const float* r = src + (size_t)(kl0 + tid) * D_;
#pragma unroll
    for (int i = 0; i < 4; ++i) {
        float4 v = *(const float4*)(r + i * 4);
        tile[tid][i*4+0] = v.x; tile[tid][i*4+1] = v.y;
        tile[tid][i*4+2] = v.z; tile[tid][i*4+3] = v.w;
    }
    __syncthreads();
    const int d = tid & 15, ch = tid >> 4;
    uint32_t hx[8];
#pragma unroll
    for (int p = 0; p < 8; ++p) {
        float f0 = tile[ch * 16 + 2*p][d];
        float f1 = tile[ch * 16 + 2*p + 1][d];
        hx[p] = h2u(__floats2half2_rn(f0, f1));
    }
    size_t off = (size_t)d * KL_ + kl0 + ch * 16;
    *(uint4*)(dh + off)     = make_uint4(hx[0], hx[1], hx[2], hx[3]);
    *(uint4*)(dh + off + 8) = make_uint4(hx[4], hx[5], hx[6], hx[7]);
}

// =====================================================================
// Kernel 3: sync-free tensor-core attention. No shared memory at all.
// Bias is loaded per-thread directly into the S accumulator init, so
// one mma produces 0.25*QK + bias (0.25 pre-folded into Q).
// =====================================================================
__global__ __launch_bounds__(256, 2)
void attn_mma_kernel(const float* __restrict__ pos_bias) {
    const int h  = blockIdx.y;
    const int q0 = blockIdx.x * 64;
    const int tid = threadIdx.x;
    const int wid = tid >> 5, lane = tid & 31;
    const int b = wid & 3, qh = wid >> 2;
    const int g = lane >> 2, tg = lane & 3;
    const int bh = b * NH_ + h;

    uint32_t qaH[2][4];
    {
        const __half* Qh = g_q16h + ((size_t)bh * QL_ + q0 + qh * 32) * DK_;
#pragma unroll
        for (int mt = 0; mt < 2; ++mt) {
            int r0 = mt * 16 + g;
            qaH[mt][0] = *(const uint32_t*)(Qh + (size_t)r0 * 16 + 2*tg);
            qaH[mt][1] = *(const uint32_t*)(Qh + (size_t)(r0+8) * 16 + 2*tg);
            qaH[mt][2] = *(const uint32_t*)(Qh + (size_t)r0 * 16 + 2*tg + 8);
            qaH[mt][3] = *(const uint32_t*)(Qh + (size_t)(r0+8) * 16 + 2*tg + 8);
        }
    }

    float O[2][2][4];
#pragma unroll
    for (int a = 0; a < 2; ++a)
#pragma unroll
        for (int c = 0; c < 2; ++c)
#pragma unroll
            for (int e = 0; e < 4; ++e) O[a][c][e] = 0.f;
    float l[2][2] = {{0.f, 0.f}, {0.f, 0.f}};

    const __half* Kp  = g_k16 + (size_t)bh * KL_ * DK_;
    const __half* Vhp = g_vth + (size_t)bh * DK_ * KL_;

    // this warp's 4 bias row pointers (rows mt*16+g, mt*16+g+8), col 2*tg
    const float* brow[2][2];
    {
        const float* Bw_ = pos_bias + ((size_t)h * QL_ + q0 + qh * 32) * KL_ + 2 * tg;
#pragma unroll
        for (int mt = 0; mt < 2; ++mt) {
            brow[mt][0] = Bw_ + (size_t)(mt * 16 + g) * KL_;
            brow[mt][1] = Bw_ + (size_t)(mt * 16 + g + 8) * KL_;
        }
    }

    for (int kt = 0; kt < KL_; kt += 32) {
        // ---- batch ALL loads for this tile: bias (DRAM) first, then K/V (L2) ----
        float2 bfr[2][4][2];
#pragma unroll
        for (int mt = 0; mt < 2; ++mt)
#pragma unroll
            for (int rr = 0; rr < 2; ++rr) {
                const float* rp = brow[mt][rr] + kt;
#pragma unroll
                for (int jn = 0; jn < 4; ++jn)
                    bfr[mt][jn][rr] = *(const float2*)(rp + jn * 8);
            }
        uint32_t kb[4][2];
#pragma unroll
        for (int jn = 0; jn < 4; ++jn) {
            const __half* kp = Kp + (size_t)(kt + jn * 8 + g) * 16;
            kb[jn][0] = *(const uint32_t*)(kp + 2 * tg);
            kb[jn][1] = *(const uint32_t*)(kp + 2 * tg + 8);
        }
        uint32_t vbr[2][2][2];
#pragma unroll
        for (int dn = 0; dn < 2; ++dn) {
            const __half* vb = Vhp + (size_t)(dn * 8 + g) * KL_ + kt;
#pragma unroll
            for (int kk = 0; kk < 2; ++kk) {
                vbr[dn][kk][0] = *(const uint32_t*)(vb + kk * 16 + 2 * tg);
                vbr[dn][kk][1] = *(const uint32_t*)(vb + kk * 16 + 2 * tg + 8);
            }
        }

        // ---- S = 0.25*QK^T + bias (bias in accumulator init), P = exp(S) ----
        uint32_t ph[2][4][2];
#pragma unroll
        for (int jn = 0; jn < 4; ++jn) {
#pragma unroll
            for (int mt = 0; mt < 2; ++mt) {
                float S[4] = {bfr[mt][jn][0].x, bfr[mt][jn][0].y,
                              bfr[mt][jn][1].x, bfr[mt][jn][1].y};
                mma16816(S, qaH[mt], kb[jn][0], kb[jn][1]);
                float p0 = __expf(S[0]);
                float p1 = __expf(S[1]);
                float p2 = __expf(S[2]);
                float p3 = __expf(S[3]);
                l[mt][0] += p0 + p1;
                l[mt][1] += p2 + p3;
                ph[mt][jn][0] = h2u(__floats2half2_rn(p0, p1));
                ph[mt][jn][1] = h2u(__floats2half2_rn(p2, p3));
            }
        }

        // ---- O += P @ V^T ----
#pragma unroll
        for (int dn = 0; dn < 2; ++dn) {
#pragma unroll
            for (int kk = 0; kk < 2; ++kk) {
#pragma unroll
                for (int mt = 0; mt < 2; ++mt) {
                    uint32_t aH[4] = {ph[mt][2*kk][0], ph[mt][2*kk][1],
                                      ph[mt][2*kk+1][0], ph[mt][2*kk+1][1]};
                    mma16816(O[mt][dn], aH, vbr[dn][kk][0], vbr[dn][kk][1]);
                }
            }
        }
    }

#pragma unroll
    for (int mt = 0; mt < 2; ++mt)
#pragma unroll
        for (int r = 0; r < 2; ++r) {
            float v = l[mt][r];
            v += __shfl_xor_sync(0xffffffffu, v, 1);
            v += __shfl_xor_sync(0xffffffffu, v, 2);
            l[mt][r] = 1.0f / v;
        }

    float* op = g_ao + (size_t)b * QL_ * D_;
#pragma unroll
    for (int mt = 0; mt < 2; ++mt) {
        int row0 = q0 + qh * 32 + mt * 16 + g;
#pragma unroll
        for (int dn = 0; dn < 2; ++dn) {
            int col = h * 16 + dn * 8 + 2 * tg;
            float2 s0 = make_float2(O[mt][dn][0] * l[mt][0],
                                    O[mt][dn][1] * l[mt][0]);
            float2 s1 = make_float2(O[mt][dn][2] * l[mt][1],
                                    O[mt][dn][3] * l[mt][1]);
            *(float2*)(op + (size_t)row0 * D_ + col) = s0;
            *(float2*)(op + (size_t)(row0 + 8) * D_ + col) = s1;
        }
    }
}

// =====================================================================
extern "C" void kernel_launch(void* const* d_in, const int* in_sizes, int n_in,
                              void* d_out, int out_size) {
    const float* x        = (const float*)d_in[0];
    const float* conv_w   = (const float*)d_in[1];
    const float* conv_b   = (const float*)d_in[2];
    const float* gn_g     = (const float*)d_in[3];
    const float* gn_b     = (const float*)d_in[4];
    const float* wq       = (const float*)d_in[5];
    const float* bq       = (const float*)d_in[6];
    const float* wkv      = (const float*)d_in[7];
    const float* bkv      = (const float*)d_in[8];
    const float* pos_bias = (const float*)d_in[9];
    const float* proj_w   = (const float*)d_in[10];
    const float* proj_b   = (const float*)d_in[11];
    float* out = (float*)d_out;

    conv_gn_mma_kernel<<<dim3(4, 36), 256>>>(x, conv_w, conv_b, gn_g, gn_b);
    gemm_mma_kernel<0><<<dim3(4, 8, 4), 256>>>(x, wq, bq, nullptr);
    gemm_mma_kernel<1><<<dim3(8, 18, 4), 256>>>(nullptr, wkv, bkv, nullptr);
    vtrans_kernel<<<dim3(64, 9), 256>>>();
    attn_mma_kernel<<<dim3(16, 16), 256>>>(pos_bias);
    gemm_mma_kernel<2><<<dim3(4, 8, 4), 256>>>(nullptr, proj_w, proj_b, out);
}

// round 12
// speedup vs baseline: 1.0884x; 1.0884x over previous
#include <cuda_runtime.h>
#include <cuda_fp16.h>
#include <stdint.h>
#include <math.h>

// ---------------- problem constants ----------------
constexpr int B_  = 4;
constexpr int S_  = 9;
constexpr int D_  = 256;
constexpr int NH_ = 16;
constexpr int DK_ = 16;
constexpr int QL_ = 1024;   // 32*32
constexpr int KL_ = 2304;   // 9*16*16
constexpr float LOG2E = 1.4426950408889634f;

// ---------------- scratch (no cudaMalloc allowed) ----------------
__device__ float  g_vn [B_ * KL_ * D_];         // (b, kl, d)  post conv+GN
__device__ float  g_v  [B_ * KL_ * D_];         // (b, kl, d)  V fp32 (pre-transpose)
__device__ float  g_ao [B_ * QL_ * D_];         // (b, q, h*dk) attention output
__device__ __half g_q16h[B_ * NH_ * QL_ * DK_]; // (bh, q, dk) Q fp16 (x 0.25*log2e)
__device__ __half g_k16 [B_ * NH_ * KL_ * DK_]; // (bh, kl, dk) K fp16
__device__ __half g_vth [B_ * NH_ * DK_ * KL_]; // (bh, dk, kl) V^T fp16

__device__ __forceinline__ uint32_t h2u(__half2 h) {
    return *reinterpret_cast<uint32_t*>(&h);
}

// fp32-accum fp16 mma: D = A(16x16) * B(16x8) + D
__device__ __forceinline__ void mma16816(float* c, const uint32_t* a,
                                         uint32_t b0, uint32_t b1) {
    asm volatile(
        "mma.sync.aligned.m16n8k16.row.col.f32.f16.f16.f32 "
        "{%0,%1,%2,%3}, {%4,%5,%6,%7}, {%8,%9}, {%0,%1,%2,%3};\n"
        : "+f"(c[0]), "+f"(c[1]), "+f"(c[2]), "+f"(c[3])
        : "r"(a[0]), "r"(a[1]), "r"(a[2]), "r"(a[3]), "r"(b0), "r"(b1));
}

__device__ __forceinline__ void split2(float a, float b, __half2& h, __half2& l) {
    h = __floats2half2_rn(a, b);
    l = __floats2half2_rn(a - __low2float(h), b - __high2float(h));
}

// =====================================================================
// Kernel 1: HMMA conv(2x2,s2) + bias + fused GroupNorm.
// 2-term compensation: Ah*Bh + Ah*Bl. grid=(4, 36), block=256.
// =====================================================================
__global__ __launch_bounds__(256, 1)
void conv_gn_mma_kernel(const float* __restrict__ x,
                        const float* __restrict__ cw,
                        const float* __restrict__ cb,
                        const float* __restrict__ gng,
                        const float* __restrict__ gnb) {
    const int nb  = blockIdx.x;              // oc quarter (64 oc)
    const int bs  = blockIdx.y;              // image
    const int bb  = bs / 9, ss = bs % 9;
    const int tid = threadIdx.x;
    const int wid = tid >> 5, lane = tid & 31;
    const int g   = lane >> 2, tg = lane & 3;
    const int wm  = wid & 3, wn = wid >> 2;
    const int pi  = tid >> 4, pj = tid & 15;
    const int n0  = nb * 64;

    __shared__ __half Ah[256][36];
    __shared__ __half Bh[64][36],  Bl[64][36];
    __shared__ float  sred[8];
    __shared__ float  sstat[8];

    if (tid < 8) sred[tid] = 0.f;

    float acc[4][4][4];
#pragma unroll
    for (int a = 0; a < 4; ++a)
#pragma unroll
        for (int b = 0; b < 4; ++b)
#pragma unroll
            for (int e = 0; e < 4; ++e) acc[a][b][e] = 0.f;

    const float* xb = x + (size_t)bs * (256 * 1024);

    for (int ch = 0; ch < 32; ++ch) {
        const int k0 = ch * 32;
        __syncthreads();
        const float* xrow = xb + (size_t)(ch * 8) * 1024 + (2 * pi) * 32 + 2 * pj;
#pragma unroll
        for (int kk = 0; kk < 32; kk += 2) {
            const int ic = kk >> 2, dy = (kk >> 1) & 1;
            float2 v = *(const float2*)(xrow + ic * 1024 + dy * 32);
            *(__half2*)&Ah[tid][kk] = __floats2half2_rn(v.x, v.y);
        }
#pragma unroll
        for (int i = 0; i < 2; ++i) {
            const int idx = tid * 2 + i;
            const int oc = idx >> 3, j = (idx & 7) * 4;
            float4 wv = *(const float4*)(cw + (size_t)(n0 + oc) * 1024 + k0 + j);
            __half2 h01, l01, h23, l23;
            split2(wv.x, wv.y, h01, l01);
            split2(wv.z, wv.w, h23, l23);
            *(__half2*)&Bh[oc][j]     = h01;
            *(__half2*)&Bh[oc][j + 2] = h23;
            *(__half2*)&Bl[oc][j]     = l01;
            *(__half2*)&Bl[oc][j + 2] = l23;
        }
        __syncthreads();

#pragma unroll
        for (int ks = 0; ks < 2; ++ks) {
            const int kc = ks * 16 + 2 * tg;
            uint32_t aH[4][4];
#pragma unroll
            for (int mt = 0; mt < 4; ++mt) {
                const int r = wm * 64 + mt * 16 + g;
                aH[mt][0] = *(uint32_t*)&Ah[r][kc];
                aH[mt][1] = *(uint32_t*)&Ah[r + 8][kc];
                aH[mt][2] = *(uint32_t*)&Ah[r][kc + 8];
                aH[mt][3] = *(uint32_t*)&Ah[r + 8][kc + 8];
            }
#pragma unroll
            for (int nt = 0; nt < 4; ++nt) {
                const int c = wn * 32 + nt * 8 + g;
                uint32_t bh0 = *(uint32_t*)&Bh[c][kc];
                uint32_t bh1 = *(uint32_t*)&Bh[c][kc + 8];
                uint32_t bl0 = *(uint32_t*)&Bl[c][kc];
                uint32_t bl1 = *(uint32_t*)&Bl[c][kc + 8];
#pragma unroll
                for (int mt = 0; mt < 4; ++mt) {
                    mma16816(acc[mt][nt], aH[mt], bh0, bh1);
                    mma16816(acc[mt][nt], aH[mt], bl0, bl1);
                }
            }
        }
    }

    float gsum[2] = {0.f, 0.f}, gsq[2] = {0.f, 0.f};
#pragma unroll
    for (int nt = 0; nt < 4; ++nt) {
        const int col = n0 + wn * 32 + nt * 8 + 2 * tg;
        const float b0 = cb[col], b1 = cb[col + 1];
#pragma unroll
        for (int mt = 0; mt < 4; ++mt) {
            float* c = acc[mt][nt];
            c[0] += b0; c[1] += b1; c[2] += b0; c[3] += b1;
            gsum[nt >> 1] += (c[0] + c[1]) + (c[2] + c[3]);
            gsq[nt >> 1]  += (c[0]*c[0] + c[1]*c[1]) + (c[2]*c[2] + c[3]*c[3]);
        }
    }
#pragma unroll
    for (int i = 0; i < 2; ++i)
#pragma unroll
        for (int off = 16; off; off >>= 1) {
            gsum[i] += __shfl_xor_sync(0xffffffffu, gsum[i], off);
            gsq[i]  += __shfl_xor_sync(0xffffffffu, gsq[i],  off);
        }
    if (lane == 0) {
#pragma unroll
        for (int i = 0; i < 2; ++i) {
            const int gi = wn * 2 + i;
            atomicAdd(&sred[gi * 2],     gsum[i]);
            atomicAdd(&sred[gi * 2 + 1], gsq[i]);
        }
    }
    __syncthreads();
    if (tid < 4) {
        const float mu  = sred[tid * 2] * (1.f / 4096.f);
        const float var = sred[tid * 2 + 1] * (1.f / 4096.f) - mu * mu;
        sstat[tid * 2]     = mu;
        sstat[tid * 2 + 1] = rsqrtf(var + 1e-5f);
    }
    __syncthreads();

    float* dstb = g_vn + ((size_t)bb * KL_ + ss * 256) * 256;
#pragma unroll
    for (int nt = 0; nt < 4; ++nt) {
        const int gi = wn * 2 + (nt >> 1);
        const float mu = sstat[gi * 2], rstd = sstat[gi * 2 + 1];
        const int col = n0 + wn * 32 + nt * 8 + 2 * tg;
        const float s0 = rstd * gng[col],     o0 = gnb[col]     - mu * s0;
        const float s1 = rstd * gng[col + 1], o1 = gnb[col + 1] - mu * s1;
#pragma unroll
        for (int mt = 0; mt < 4; ++mt) {
            const int r = wm * 64 + mt * 16 + g;
            const float* c = acc[mt][nt];
            *(float2*)(dstb + (size_t)r * 256 + col) =
                make_float2(c[0] * s0 + o0, c[1] * s1 + o1);
            *(float2*)(dstb + (size_t)(r + 8) * 256 + col) =
                make_float2(c[2] * s0 + o0, c[3] * s1 + o1);
        }
    }
}

// =====================================================================
// Tensor-core batched GEMM, tile M=128 N=64, K=256 in chunks of 32.
// MODE 0: Q = x[:,4]^T @ wq  -> fp16 head-major, scaled x (0.25*log2e)
//         2-term (output rounded to fp16 anyway)
// MODE 1: KV = g_vn @ wkv    -> K fp16 head-major, V fp32; 2-term
// MODE 2: proj = g_ao @ proj_w -> fp32 transposed store; 3-term
// =====================================================================
template <int MODE>
__global__ __launch_bounds__(256, 2)
void gemm_mma_kernel(const float* __restrict__ Aext,
                     const float* __restrict__ Bw,
                     const float* __restrict__ bias,
                     float* __restrict__ Cext) {
    constexpr int N = (MODE == 1) ? 512 : 256;
    constexpr bool COMP_A = (MODE == 2);

    const int b  = blockIdx.z;
    const int n0 = blockIdx.x * 64;
    const int m0 = blockIdx.y * 128;
    const int tid = threadIdx.x;
    const int wid = tid >> 5, lane = tid & 31;
    const int g = lane >> 2, tg = lane & 3;
    const int wm = wid & 3, wn = wid >> 2;

    __shared__ __half Ah[128][36], Al[128][36];
    __shared__ __half Bh[64][36],  Bl[64][36];

    const float* Ab;
    if (MODE == 0)      Ab = Aext + ((size_t)(b * 9 + 4)) * (256 * 1024);
    else if (MODE == 1) Ab = g_vn + (size_t)b * (KL_ * D_);
    else                Ab = g_ao + (size_t)b * (QL_ * D_);

    float acc[2][4][4];
#pragma unroll
    for (int a = 0; a < 2; ++a)
#pragma unroll
        for (int c = 0; c < 4; ++c)
#pragma unroll
            for (int e = 0; e < 4; ++e) acc[a][c][e] = 0.f;

    for (int k0 = 0; k0 < 256; k0 += 32) {
        __syncthreads();
        // ---- A staging ----
        if (MODE == 0) {
            const int kk = tid >> 6, mloc = (tid & 63) * 2;
#pragma unroll
            for (int i = 0; i < 8; ++i) {
                const int k = kk + i * 4;
                float2 v = *(const float2*)(Ab + (size_t)(k0 + k) * 1024 + m0 + mloc);
                __half2 h = __floats2half2_rn(v.x, v.y);
                Ah[mloc][k]     = __low2half(h);
                Ah[mloc + 1][k] = __high2half(h);
            }
        } else {
            const int arow = tid >> 3, c4 = (tid & 7) * 4;
#pragma unroll
            for (int i = 0; i < 4; ++i) {
                const int r = arow + i * 32;
                float4 a4 = *(const float4*)(Ab + (size_t)(m0 + r) * 256 + k0 + c4);
                if (COMP_A) {
                    __half2 h01, l01, h23, l23;
                    split2(a4.x, a4.y, h01, l01);
                    split2(a4.z, a4.w, h23, l23);
                    *(__half2*)&Ah[r][c4]     = h01;
                    *(__half2*)&Ah[r][c4 + 2] = h23;
                    *(__half2*)&Al[r][c4]     = l01;
                    *(__half2*)&Al[r][c4 + 2] = l23;
                } else {
                    *(__half2*)&Ah[r][c4]     = __floats2half2_rn(a4.x, a4.y);
                    *(__half2*)&Ah[r][c4 + 2] = __floats2half2_rn(a4.z, a4.w);
                }
            }
        }
        // ---- B staging ----
        {
            const int bk2 = (tid >> 4) * 2, bn4 = (tid & 15) * 4;
            float4 u = *(const float4*)(Bw + (size_t)(k0 + bk2) * N + n0 + bn4);
            float4 w = *(const float4*)(Bw + (size_t)(k0 + bk2 + 1) * N + n0 + bn4);
            float uu[4] = {u.x, u.y, u.z, u.w};
            float wwv[4] = {w.x, w.y, w.z, w.w};
#pragma unroll
            for (int j = 0; j < 4; ++j) {
                __half2 h, l;
                split2(uu[j], wwv[j], h, l);
                *(__half2*)&Bh[bn4 + j][bk2] = h;
                *(__half2*)&Bl[bn4 + j][bk2] = l;
            }
        }
        __syncthreads();

#pragma unroll
        for (int ks = 0; ks < 2; ++ks) {
            const int kc = ks * 16 + 2 * tg;
            uint32_t aH[2][4], aL[2][4];
#pragma unroll
            for (int mt = 0; mt < 2; ++mt) {
                const int r = wm * 32 + mt * 16 + g;
                aH[mt][0] = *(uint32_t*)&Ah[r][kc];
                aH[mt][1] = *(uint32_t*)&Ah[r + 8][kc];
                aH[mt][2] = *(uint32_t*)&Ah[r][kc + 8];
                aH[mt][3] = *(uint32_t*)&Ah[r + 8][kc + 8];
                if (COMP_A) {
                    aL[mt][0] = *(uint32_t*)&Al[r][kc];
                    aL[mt][1] = *(uint32_t*)&Al[r + 8][kc];
                    aL[mt][2] = *(uint32_t*)&Al[r][kc + 8];
                    aL[mt][3] = *(uint32_t*)&Al[r + 8][kc + 8];
                }
            }
#pragma unroll
            for (int nt = 0; nt < 4; ++nt) {
                const int c = wn * 32 + nt * 8 + g;
                uint32_t bh0 = *(uint32_t*)&Bh[c][kc];
                uint32_t bh1 = *(uint32_t*)&Bh[c][kc + 8];
                uint32_t bl0 = *(uint32_t*)&Bl[c][kc];
                uint32_t bl1 = *(uint32_t*)&Bl[c][kc + 8];
#pragma unroll
                for (int mt = 0; mt < 2; ++mt) {
                    mma16816(acc[mt][nt], aH[mt], bh0, bh1);
                    if (COMP_A) mma16816(acc[mt][nt], aL[mt], bh0, bh1);
                    mma16816(acc[mt][nt], aH[mt], bl0, bl1);
                }
            }
        }
    }

    // ---- epilogue ----
#pragma unroll
    for (int nt = 0; nt < 4; ++nt) {
        const int c = n0 + wn * 32 + nt * 8 + 2 * tg;
        const float bl0 = bias[c], bl1 = bias[c + 1];
#pragma unroll
        for (int mt = 0; mt < 2; ++mt) {
            const int r0 = m0 + wm * 32 + mt * 16 + g, r1 = r0 + 8;
            const float* a = acc[mt][nt];
            const float v00 = a[0] + bl0, v01 = a[1] + bl1;
            const float v10 = a[2] + bl0, v11 = a[3] + bl1;
            if (MODE == 2) {
                Cext[((size_t)b * 256 + c) * 1024 + r0]     = v00;
                Cext[((size_t)b * 256 + c + 1) * 1024 + r0] = v01;
                Cext[((size_t)b * 256 + c) * 1024 + r1]     = v10;
                Cext[((size_t)b * 256 + c + 1) * 1024 + r1] = v11;
            } else if (MODE == 0) {
                // fold softmax 0.25 and log2e into Q
                constexpr float QS = 0.25f * LOG2E;
                const int hh = c >> 4, dk = c & 15;
                __half2 h0 = __floats2half2_rn(v00 * QS, v01 * QS);
                __half2 h1 = __floats2half2_rn(v10 * QS, v11 * QS);
                size_t o0 = ((size_t)(b * NH_ + hh) * QL_ + r0) * DK_ + dk;
                size_t o1 = ((size_t)(b * NH_ + hh) * QL_ + r1) * DK_ + dk;
                *(uint32_t*)(g_q16h + o0) = h2u(h0);
                *(uint32_t*)(g_q16h + o1) = h2u(h1);
            } else { // MODE 1
                if (c < 256) {
                    const int hh = c >> 4, dk = c & 15;
                    __half2 h0 = __floats2half2_rn(v00, v01);
                    __half2 h1 = __floats2half2_rn(v10, v11);
                    size_t o0 = ((size_t)(b * NH_ + hh) * KL_ + r0) * DK_ + dk;
                    size_t o1 = ((size_t)(b * NH_ + hh) * KL_ + r1) * DK_ + dk;
                    *(uint32_t*)(g_k16 + o0) = h2u(h0);
                    *(uint32_t*)(g_k16 + o1) = h2u(h1);
                } else {
                    const int d = c - 256;
                    float* C = g_v + (size_t)b * (KL_ * D_);
                    *(float2*)(C + (size_t)r0 * 256 + d) = make_float2(v00, v01);
                    *(float2*)(C + (size_t)r1 * 256 + d) = make_float2(v10, v11);
                }
            }
        }
    }
}

// =====================================================================
// V transpose: fp32 (b,kl,d) -> fp16 (bh, dk, kl)
// grid = (64 bh, 9 kl-chunks), block = 256
// =====================================================================
__global__ void vtrans_kernel() {
    const int bh = blockIdx.x;
    const int b = bh >> 4, h = bh & 15;
    const int kl0 = blockIdx.y * 256;
    const int tid = threadIdx.x;
    __shared__ float tile[256][17];
    const float* src = g_v + (size_t)b * KL_ * D_ + h * 16;
    __half* dh = g_vth + (size_t)bh * DK_ * KL_;

    const float* r = src + (size_t)(kl0 + tid) * D_;
#pragma unroll
    for (int i = 0; i < 4; ++i) {
        float4 v = *(const float4*)(r + i * 4);
        tile[tid][i*4+0] = v.x; tile[tid][i*4+1] = v.y;
        tile[tid][i*4+2] = v.z; tile[tid][i*4+3] = v.w;
    }
    __syncthreads();
    const int d = tid & 15, ch = tid >> 4;
    uint32_t hx[8];
#pragma unroll
    for (int p = 0; p < 8; ++p) {
        float f0 = tile[ch * 16 + 2*p][d];
        float f1 = tile[ch * 16 + 2*p + 1][d];
        hx[p] = h2u(__floats2half2_rn(f0, f1));
    }
    size_t off = (size_t)d * KL_ + kl0 + ch * 16;
    *(uint4*)(dh + off)     = make_uint4(hx[0], hx[1], hx[2], hx[3]);
    *(uint4*)(dh + off + 8) = make_uint4(hx[4], hx[5], hx[6], hx[7]);
}

// =====================================================================
// Kernel 3: tensor-core attention. Staged smem bias (shared across the
// 4 batch-warps), DOUBLE-BUFFERED -> one __syncthreads per tile.
// Bias (x log2e) initializes the S accumulator; Q carries 0.25*log2e,
// so softmax is a bare exp2f.
// =====================================================================
__global__ __launch_bounds__(256, 2)
void attn_mma_kernel(const float* __restrict__ pos_bias) {
    const int h  = blockIdx.y;
    const int q0 = blockIdx.x * 64;
    const int tid = threadIdx.x;
    const int wid = tid >> 5, lane = tid & 31;
    const int b = wid & 3, qh = wid >> 2;
    const int g = lane >> 2, tg = lane & 3;
    const int bh = b * NH_ + h;

    __shared__ float sbias[2][4][4][32][4];  // [buf][mtile16][jn][lane][c]

    uint32_t qaH[2][4];
    {
        const __half* Qh = g_q16h + ((size_t)bh * QL_ + q0 + qh * 32) * DK_;
#pragma unroll
        for (int mt = 0; mt < 2; ++mt) {
            int r0 = mt * 16 + g;
            qaH[mt][0] = *(const uint32_t*)(Qh + (size_t)r0 * 16 + 2*tg);
            qaH[mt][1] = *(const uint32_t*)(Qh + (size_t)(r0+8) * 16 + 2*tg);
            qaH[mt][2] = *(const uint32_t*)(Qh + (size_t)r0 * 16 + 2*tg + 8);
            qaH[mt][3] = *(const uint32_t*)(Qh + (size_t)(r0+8) * 16 + 2*tg + 8);
        }
    }

    float O[2][2][4];
#pragma unroll
    for (int a = 0; a < 2; ++a)
#pragma unroll
        for (int c = 0; c < 2; ++c)
#pragma unroll
            for (int e = 0; e < 4; ++e) O[a][c][e] = 0.f;
    float l[2][2] = {{0.f, 0.f}, {0.f, 0.f}};

    const __half* Kp  = g_k16 + (size_t)bh * KL_ * DK_;
    const __half* Vhp = g_vth + (size_t)bh * DK_ * KL_;
    const float*  Bp  = pos_bias + ((size_t)h * QL_ + q0) * KL_;

    const int fi0 = tid * 2;
    const int brow0 = fi0 >> 3,       bcg0 = fi0 & 7;
    const int brow1 = (fi0 + 1) >> 3, bcg1 = (fi0 + 1) & 7;

    float4 bp0 = *(const float4*)(Bp + (size_t)brow0 * KL_ + 0 + bcg0 * 4);
    float4 bp1 = *(const float4*)(Bp + (size_t)brow1 * KL_ + 0 + bcg1 * 4);

    int buf = 0;
    for (int kt = 0; kt < KL_; kt += 32, buf ^= 1) {
        // stage prefetched bias tile (x log2e) into smem buffer `buf`
        {
            float (*sb)[4][32][4] = sbias[buf];
            int jn = bcg0 >> 1;
            int L  = (brow0 & 7) * 4 + (bcg0 & 1) * 2;
            int e  = ((brow0 >> 3) & 1) * 2;
            float* d0 = &sb[brow0 >> 4][jn][L][e];
            d0[0] = bp0.x * LOG2E; d0[1] = bp0.y * LOG2E;
            float* d1 = &sb[brow0 >> 4][jn][L + 1][e];
            d1[0] = bp0.z * LOG2E; d1[1] = bp0.w * LOG2E;
            jn = bcg1 >> 1;
            L  = (brow1 & 7) * 4 + (bcg1 & 1) * 2;
            e  = ((brow1 >> 3) & 1) * 2;
            d0 = &sb[brow1 >> 4][jn][L][e];
            d0[0] = bp1.x * LOG2E; d0[1] = bp1.y * LOG2E;
            d1 = &sb[brow1 >> 4][jn][L + 1][e];
            d1[0] = bp1.z * LOG2E; d1[1] = bp1.w * LOG2E;
        }

        // prefetch NEXT bias tile (overlaps barrier + compute)
        if (kt + 32 < KL_) {
            bp0 = *(const float4*)(Bp + (size_t)brow0 * KL_ + (kt + 32) + bcg0 * 4);
            bp1 = *(const float4*)(Bp + (size_t)brow1 * KL_ + (kt + 32) + bcg1 * 4);
        }

        // batch all K/V loads for this tile
        uint32_t kb[4][2];
#pragma unroll
        for (int jn = 0; jn < 4; ++jn) {
            const __half* kp = Kp + (size_t)(kt + jn * 8 + g) * 16;
            kb[jn][0] = *(const uint32_t*)(kp + 2 * tg);
            kb[jn][1] = *(const uint32_t*)(kp + 2 * tg + 8);
        }
        uint32_t vbr[2][2][2];
#pragma unroll
        for (int dn = 0; dn < 2; ++dn) {
            const __half* vb = Vhp + (size_t)(dn * 8 + g) * KL_ + kt;
#pragma unroll
            for (int kk = 0; kk < 2; ++kk) {
                vbr[dn][kk][0] = *(const uint32_t*)(vb + kk * 16 + 2 * tg);
                vbr[dn][kk][1] = *(const uint32_t*)(vb + kk * 16 + 2 * tg + 8);
            }
        }

        __syncthreads();   // the ONLY sync per tile (double buffer)

        uint32_t ph[2][4][2];
#pragma unroll
        for (int jn = 0; jn < 4; ++jn) {
#pragma unroll
            for (int mt = 0; mt < 2; ++mt) {
                float4 bf = *(const float4*)&sbias[buf][qh * 2 + mt][jn][lane][0];
                float S[4] = {bf.x, bf.y, bf.z, bf.w};
                mma16816(S, qaH[mt], kb[jn][0], kb[jn][1]);
                float p0 = exp2f(S[0]);
                float p1 = exp2f(S[1]);
                float p2 = exp2f(S[2]);
                float p3 = exp2f(S[3]);
                l[mt][0] += p0 + p1;
                l[mt][1] += p2 + p3;
                ph[mt][jn][0] = h2u(__floats2half2_rn(p0, p1));
                ph[mt][jn][1] = h2u(__floats2half2_rn(p2, p3));
            }
        }

#pragma unroll
        for (int dn = 0; dn < 2; ++dn) {
#pragma unroll
            for (int kk = 0; kk < 2; ++kk) {
#pragma unroll
                for (int mt = 0; mt < 2; ++mt) {
                    uint32_t aH[4] = {ph[mt][2*kk][0], ph[mt][2*kk][1],
                                      ph[mt][2*kk+1][0], ph[mt][2*kk+1][1]};
                    mma16816(O[mt][dn], aH, vbr[dn][kk][0], vbr[dn][kk][1]);
                }
            }
        }
    }

#pragma unroll
    for (int mt = 0; mt < 2; ++mt)
#pragma unroll
        for (int r = 0; r < 2; ++r) {
            float v = l[mt][r];
            v += __shfl_xor_sync(0xffffffffu, v, 1);
            v += __shfl_xor_sync(0xffffffffu, v, 2);
            l[mt][r] = 1.0f / v;
        }

    float* op = g_ao + (size_t)b * QL_ * D_;
#pragma unroll
    for (int mt = 0; mt < 2; ++mt) {
        int row0 = q0 + qh * 32 + mt * 16 + g;
#pragma unroll
        for (int dn = 0; dn < 2; ++dn) {
            int col = h * 16 + dn * 8 + 2 * tg;
            float2 s0 = make_float2(O[mt][dn][0] * l[mt][0],
                                    O[mt][dn][1] * l[mt][0]);
            float2 s1 = make_float2(O[mt][dn][2] * l[mt][1],
                                    O[mt][dn][3] * l[mt][1]);
            *(float2*)(op + (size_t)row0 * D_ + col) = s0;
            *(float2*)(op + (size_t)(row0 + 8) * D_ + col) = s1;
        }
    }
}

// =====================================================================
extern "C" void kernel_launch(void* const* d_in, const int* in_sizes, int n_in,
                              void* d_out, int out_size) {
    const float* x        = (const float*)d_in[0];
    const float* conv_w   = (const float*)d_in[1];
    const float* conv_b   = (const float*)d_in[2];
    const float* gn_g     = (const float*)d_in[3];
    const float* gn_b     = (const float*)d_in[4];
    const float* wq       = (const float*)d_in[5];
    const float* bq       = (const float*)d_in[6];
    const float* wkv      = (const float*)d_in[7];
    const float* bkv      = (const float*)d_in[8];
    const float* pos_bias = (const float*)d_in[9];
    const float* proj_w   = (const float*)d_in[10];
    const float* proj_b   = (const float*)d_in[11];
    float* out = (float*)d_out;

    conv_gn_mma_kernel<<<dim3(4, 36), 256>>>(x, conv_w, conv_b, gn_g, gn_b);
    gemm_mma_kernel<0><<<dim3(4, 8, 4), 256>>>(x, wq, bq, nullptr);
    gemm_mma_kernel<1><<<dim3(8, 18, 4), 256>>>(nullptr, wkv, bkv, nullptr);
    vtrans_kernel<<<dim3(64, 9), 256>>>();
    attn_mma_kernel<<<dim3(16, 16), 256>>>(pos_bias);
    gemm_mma_kernel<2><<<dim3(4, 8, 4), 256>>>(nullptr, proj_w, proj_b, out);
}